// round 1
// baseline (speedup 1.0000x reference)
#include <cuda_runtime.h>
#include <math.h>

// ---------------------------------------------------------------------------
// Problem constants
//   x  : [4, 2048, 2048] f32
//   wq/wk/wv/wo : [2048, 2048] f32, applied as y = x @ W^T
//   out: [4, 2048, 2048] f32
// ---------------------------------------------------------------------------
#define D_MODEL 2048
#define SEQ     2048
#define BATCH   4
#define NHEAD   16
#define DK      128
#define M_TOT   (BATCH * SEQ)       // 8192

// Scratch buffers (allocation-free rule: __device__ globals)
__device__ float g_Q[(size_t)M_TOT * D_MODEL];
__device__ float g_K[(size_t)M_TOT * D_MODEL];
__device__ float g_V[(size_t)M_TOT * D_MODEL];
__device__ float g_C[(size_t)M_TOT * D_MODEL];

// ---------------------------------------------------------------------------
// SGEMM: C[M,N] = A[M,K] * B[N,K]^T   (both row-major, contraction over fast dim)
// Tiles: 128x128x16, 256 threads, 8x8 per-thread microtile.
// ---------------------------------------------------------------------------
#define BM 128
#define BN 128
#define BKK 16
#define PAD_LD 132   // 128 + 4 floats padding (keeps float4 alignment, breaks bank conflicts)

__global__ __launch_bounds__(256) void sgemm_nt(
    const float* __restrict__ A, const float* __restrict__ B,
    float* __restrict__ C, int M, int N, int K)
{
    __shared__ float As[BKK][PAD_LD];
    __shared__ float Bs[BKK][PAD_LD];

    const int tid  = threadIdx.x;
    const int row0 = blockIdx.y * BM;
    const int col0 = blockIdx.x * BN;

    // loader mapping: each thread loads 2 float4 from A and 2 from B per k-step
    const int ldr = tid >> 2;          // 0..63
    const int ldc = (tid & 3) << 2;    // 0,4,8,12

    const float* Aptr = A + (size_t)(row0 + ldr) * K + ldc;
    const float* Bptr = B + (size_t)(col0 + ldr) * K + ldc;

    // compute mapping
    const int tx = tid & 15;           // 0..15 -> 8 cols each
    const int ty = tid >> 4;           // 0..15 -> 8 rows each

    float acc[8][8];
    #pragma unroll
    for (int i = 0; i < 8; ++i)
        #pragma unroll
        for (int j = 0; j < 8; ++j) acc[i][j] = 0.f;

    for (int k0 = 0; k0 < K; k0 += BKK) {
        const float4 a0 = *(const float4*)(Aptr + k0);
        const float4 a1 = *(const float4*)(Aptr + (size_t)64 * K + k0);
        const float4 b0 = *(const float4*)(Bptr + k0);
        const float4 b1 = *(const float4*)(Bptr + (size_t)64 * K + k0);

        __syncthreads();   // previous iteration's readers done
        As[ldc + 0][ldr] = a0.x; As[ldc + 1][ldr] = a0.y;
        As[ldc + 2][ldr] = a0.z; As[ldc + 3][ldr] = a0.w;
        As[ldc + 0][ldr + 64] = a1.x; As[ldc + 1][ldr + 64] = a1.y;
        As[ldc + 2][ldr + 64] = a1.z; As[ldc + 3][ldr + 64] = a1.w;
        Bs[ldc + 0][ldr] = b0.x; Bs[ldc + 1][ldr] = b0.y;
        Bs[ldc + 2][ldr] = b0.z; Bs[ldc + 3][ldr] = b0.w;
        Bs[ldc + 0][ldr + 64] = b1.x; Bs[ldc + 1][ldr + 64] = b1.y;
        Bs[ldc + 2][ldr + 64] = b1.z; Bs[ldc + 3][ldr + 64] = b1.w;
        __syncthreads();

        #pragma unroll
        for (int kk = 0; kk < BKK; ++kk) {
            const float4 av0 = *(const float4*)&As[kk][ty * 8];
            const float4 av1 = *(const float4*)&As[kk][ty * 8 + 4];
            const float4 bv0 = *(const float4*)&Bs[kk][tx * 8];
            const float4 bv1 = *(const float4*)&Bs[kk][tx * 8 + 4];
            const float ar[8] = {av0.x, av0.y, av0.z, av0.w, av1.x, av1.y, av1.z, av1.w};
            const float br[8] = {bv0.x, bv0.y, bv0.z, bv0.w, bv1.x, bv1.y, bv1.z, bv1.w};
            #pragma unroll
            for (int i = 0; i < 8; ++i)
                #pragma unroll
                for (int j = 0; j < 8; ++j)
                    acc[i][j] += ar[i] * br[j];
        }
    }

    #pragma unroll
    for (int i = 0; i < 8; ++i) {
        float* crow = C + (size_t)(row0 + ty * 8 + i) * N + col0 + tx * 8;
        float4 c0 = {acc[i][0], acc[i][1], acc[i][2], acc[i][3]};
        float4 c1 = {acc[i][4], acc[i][5], acc[i][6], acc[i][7]};
        *(float4*)(crow)     = c0;
        *(float4*)(crow + 4) = c1;
    }
}

// ---------------------------------------------------------------------------
// Flash attention (fp32, online softmax).
// Grid: (SEQ/BQ, BATCH*NHEAD). Block: 256 threads.
// Per CTA: Q tile [64,128] resident; stream K/V tiles [64,128].
// Thread t: row group g = t/16 (4 q-rows), cg = t%16.
//   Phase 1 (scores): 4x4 sub-tile (rows 4g.., cols 4cg..)
//   Phase 2 (PV):     4 rows x 8 d-cols (dcol = 8*cg)
// ---------------------------------------------------------------------------
#define BQ   64
#define BKV  64
#define QST  128      // Qs row stride (accesses broadcast -> no padding needed)
#define KVST 132      // Ks/Vs row stride (padded)
#define PST  68       // Ps row stride (padded)

#define SM_FLOATS (BQ*QST + BKV*KVST + BKV*KVST + BQ*PST)   // 29440
#define SM_BYTES  (SM_FLOATS * 4)                            // 117760

__global__ __launch_bounds__(256) void flash_attn(
    const float* __restrict__ Q, const float* __restrict__ K,
    const float* __restrict__ V, float* __restrict__ O)
{
    extern __shared__ float sm[];
    float* Qs = sm;                          // [64][128]
    float* Ks = Qs + BQ * QST;               // [64][132]
    float* Vs = Ks + BKV * KVST;             // [64][132]
    float* Ps = Vs + BKV * KVST;             // [64][68]

    const int tid = threadIdx.x;
    const int qb  = blockIdx.x;              // 0..31
    const int bh  = blockIdx.y;              // 0..63
    const int b   = bh >> 4;
    const int h   = bh & 15;
    const int q0  = qb * BQ;

    // element offset of (b, s=0, h, d=0); row stride = D_MODEL
    const size_t base = (size_t)b * SEQ * D_MODEL + (size_t)h * DK;

    // load Q tile, pre-scaled by 1/sqrt(DK)
    const float qscale = 0.08838834764831845f;
    for (int i = tid; i < BQ * DK / 4; i += 256) {
        const int r  = i >> 5;               // 32 float4 per row
        const int c4 = (i & 31) << 2;
        float4 v = *(const float4*)(Q + base + (size_t)(q0 + r) * D_MODEL + c4);
        v.x *= qscale; v.y *= qscale; v.z *= qscale; v.w *= qscale;
        *(float4*)(Qs + r * QST + c4) = v;
    }

    const int g    = tid >> 4;               // 0..15
    const int cg   = tid & 15;               // 0..15
    const int qr   = g << 2;                 // first of 4 owned q-rows
    const int dcol = cg << 3;                // first of 8 owned d-cols (phase 2)

    float m_i[4], l_i[4], o[4][8];
    #pragma unroll
    for (int i = 0; i < 4; ++i) {
        m_i[i] = -1e30f; l_i[i] = 0.f;
        #pragma unroll
        for (int d = 0; d < 8; ++d) o[i][d] = 0.f;
    }

    for (int kb = 0; kb < SEQ; kb += BKV) {
        __syncthreads();  // prior PV readers of Vs (and Qs loads on first iter) done
        for (int i = tid; i < BKV * DK / 4; i += 256) {
            const int r  = i >> 5;
            const int c4 = (i & 31) << 2;
            const size_t goff = base + (size_t)(kb + r) * D_MODEL + c4;
            *(float4*)(Ks + r * KVST + c4) = *(const float4*)(K + goff);
            *(float4*)(Vs + r * KVST + c4) = *(const float4*)(V + goff);
        }
        __syncthreads();

        // ---- Phase 1: scores 4x4 ----
        float s[4][4];
        #pragma unroll
        for (int i = 0; i < 4; ++i)
            #pragma unroll
            for (int j = 0; j < 4; ++j) s[i][j] = 0.f;

        #pragma unroll 4
        for (int d = 0; d < DK; d += 4) {
            float4 qa[4], kv[4];
            #pragma unroll
            for (int i = 0; i < 4; ++i) qa[i] = *(const float4*)&Qs[(qr + i) * QST + d];
            #pragma unroll
            for (int j = 0; j < 4; ++j) kv[j] = *(const float4*)&Ks[(cg * 4 + j) * KVST + d];
            #pragma unroll
            for (int i = 0; i < 4; ++i)
                #pragma unroll
                for (int j = 0; j < 4; ++j)
                    s[i][j] += qa[i].x * kv[j].x + qa[i].y * kv[j].y
                             + qa[i].z * kv[j].z + qa[i].w * kv[j].w;
        }

        // ---- online softmax update ----
        float alpha[4];
        #pragma unroll
        for (int i = 0; i < 4; ++i) {
            float mx = fmaxf(fmaxf(s[i][0], s[i][1]), fmaxf(s[i][2], s[i][3]));
            #pragma unroll
            for (int off = 1; off < 16; off <<= 1)
                mx = fmaxf(mx, __shfl_xor_sync(0xffffffffu, mx, off));
            const float mnew = fmaxf(m_i[i], mx);
            float lsum = 0.f;
            #pragma unroll
            for (int j = 0; j < 4; ++j) {
                const float p = __expf(s[i][j] - mnew);
                Ps[(qr + i) * PST + cg * 4 + j] = p;
                lsum += p;
            }
            #pragma unroll
            for (int off = 1; off < 16; off <<= 1)
                lsum += __shfl_xor_sync(0xffffffffu, lsum, off);
            alpha[i] = __expf(m_i[i] - mnew);
            l_i[i] = l_i[i] * alpha[i] + lsum;
            m_i[i] = mnew;
        }
        __syncthreads();  // Ps fully written

        // rescale accumulators
        #pragma unroll
        for (int i = 0; i < 4; ++i)
            #pragma unroll
            for (int d = 0; d < 8; ++d) o[i][d] *= alpha[i];

        // ---- Phase 2: O += P * V ----
        #pragma unroll 2
        for (int j = 0; j < BKV; j += 4) {
            float pr[4][4];
            #pragma unroll
            for (int i = 0; i < 4; ++i) {
                const float4 pv = *(const float4*)&Ps[(qr + i) * PST + j];
                pr[i][0] = pv.x; pr[i][1] = pv.y; pr[i][2] = pv.z; pr[i][3] = pv.w;
            }
            #pragma unroll
            for (int jj = 0; jj < 4; ++jj) {
                const float4 v0 = *(const float4*)&Vs[(j + jj) * KVST + dcol];
                const float4 v1 = *(const float4*)&Vs[(j + jj) * KVST + dcol + 4];
                const float vr[8] = {v0.x, v0.y, v0.z, v0.w, v1.x, v1.y, v1.z, v1.w};
                #pragma unroll
                for (int i = 0; i < 4; ++i)
                    #pragma unroll
                    for (int d = 0; d < 8; ++d)
                        o[i][d] += pr[i][jj] * vr[d];
            }
        }
    }

    // ---- finalize: O /= l, write context in [B,S,D] layout ----
    #pragma unroll
    for (int i = 0; i < 4; ++i) {
        const float rl = 1.f / l_i[i];
        float4 u0 = {o[i][0] * rl, o[i][1] * rl, o[i][2] * rl, o[i][3] * rl};
        float4 u1 = {o[i][4] * rl, o[i][5] * rl, o[i][6] * rl, o[i][7] * rl};
        float* op = O + base + (size_t)(q0 + qr + i) * D_MODEL + dcol;
        *(float4*)(op)     = u0;
        *(float4*)(op + 4) = u1;
    }
}

// ---------------------------------------------------------------------------
// Launch
// ---------------------------------------------------------------------------
extern "C" void kernel_launch(void* const* d_in, const int* in_sizes, int n_in,
                              void* d_out, int out_size)
{
    const float* x  = (const float*)d_in[0];
    const float* wq = (const float*)d_in[1];
    const float* wk = (const float*)d_in[2];
    const float* wv = (const float*)d_in[3];
    const float* wo = (const float*)d_in[4];
    float* out = (float*)d_out;

    float *Q, *K, *V, *C;
    cudaGetSymbolAddress((void**)&Q, g_Q);
    cudaGetSymbolAddress((void**)&K, g_K);
    cudaGetSymbolAddress((void**)&V, g_V);
    cudaGetSymbolAddress((void**)&C, g_C);

    cudaFuncSetAttribute(flash_attn, cudaFuncAttributeMaxDynamicSharedMemorySize, SM_BYTES);

    const dim3 gg(D_MODEL / BN, M_TOT / BM);   // (16, 64)
    sgemm_nt<<<gg, 256>>>(x, wq, Q, M_TOT, D_MODEL, D_MODEL);
    sgemm_nt<<<gg, 256>>>(x, wk, K, M_TOT, D_MODEL, D_MODEL);
    sgemm_nt<<<gg, 256>>>(x, wv, V, M_TOT, D_MODEL, D_MODEL);

    flash_attn<<<dim3(SEQ / BQ, BATCH * NHEAD), 256, SM_BYTES>>>(Q, K, V, C);

    sgemm_nt<<<gg, 256>>>(C, wo, out, M_TOT, D_MODEL, D_MODEL);
}

// round 3
// speedup vs baseline: 1.3197x; 1.3197x over previous
#include <cuda_runtime.h>
#include <cuda_bf16.h>
#include <cstdint>
#include <math.h>

// ---------------------------------------------------------------------------
// Problem constants
// ---------------------------------------------------------------------------
#define D_MODEL 2048
#define SEQ     2048
#define BATCH   4
#define NHEAD   16
#define DK      128
#define M_TOT   (BATCH * SEQ)       // 8192
#define GK      2048
#define GN      2048

// ---------------------------------------------------------------------------
// Scratch (allocation-free rule: __device__ globals)
// ---------------------------------------------------------------------------
__device__ float g_Q[(size_t)M_TOT * D_MODEL];
__device__ float g_K[(size_t)M_TOT * D_MODEL];
__device__ float g_V[(size_t)M_TOT * D_MODEL];
__device__ float g_C[(size_t)M_TOT * D_MODEL];

__device__ __nv_bfloat16 g_xh[(size_t)M_TOT * D_MODEL];
__device__ __nv_bfloat16 g_xl[(size_t)M_TOT * D_MODEL];
__device__ __nv_bfloat16 g_ch[(size_t)M_TOT * D_MODEL];
__device__ __nv_bfloat16 g_cl[(size_t)M_TOT * D_MODEL];
__device__ __nv_bfloat16 g_wqh[(size_t)D_MODEL * D_MODEL];
__device__ __nv_bfloat16 g_wql[(size_t)D_MODEL * D_MODEL];
__device__ __nv_bfloat16 g_wkh[(size_t)D_MODEL * D_MODEL];
__device__ __nv_bfloat16 g_wkl[(size_t)D_MODEL * D_MODEL];
__device__ __nv_bfloat16 g_wvh[(size_t)D_MODEL * D_MODEL];
__device__ __nv_bfloat16 g_wvl[(size_t)D_MODEL * D_MODEL];
__device__ __nv_bfloat16 g_woh[(size_t)D_MODEL * D_MODEL];
__device__ __nv_bfloat16 g_wol[(size_t)D_MODEL * D_MODEL];

// ---------------------------------------------------------------------------
// Helpers
// ---------------------------------------------------------------------------
__device__ __forceinline__ uint32_t smem_u32(const void* p) {
    uint32_t a;
    asm("{ .reg .u64 t; cvta.to.shared.u64 t, %1; cvt.u32.u64 %0, t; }" : "=r"(a) : "l"(p));
    return a;
}
__device__ __forceinline__ void cp16(uint32_t s, const void* g) {
    asm volatile("cp.async.cg.shared.global [%0], [%1], 16;" :: "r"(s), "l"(g));
}
__device__ __forceinline__ void ldsm_x4(uint32_t (&r)[4], uint32_t addr) {
    asm volatile("ldmatrix.sync.aligned.m8n8.x4.shared.b16 {%0,%1,%2,%3}, [%4];"
        : "=r"(r[0]), "=r"(r[1]), "=r"(r[2]), "=r"(r[3]) : "r"(addr));
}
__device__ __forceinline__ void ldsm_x2(uint32_t (&r)[2], uint32_t addr) {
    asm volatile("ldmatrix.sync.aligned.m8n8.x2.shared.b16 {%0,%1}, [%2];"
        : "=r"(r[0]), "=r"(r[1]) : "r"(addr));
}
__device__ __forceinline__ void mma16816(float (&d)[4], const uint32_t (&a)[4],
                                         const uint32_t (&b)[2]) {
    asm volatile("mma.sync.aligned.m16n8k16.row.col.f32.bf16.bf16.f32 "
        "{%0,%1,%2,%3}, {%4,%5,%6,%7}, {%8,%9}, {%0,%1,%2,%3};"
        : "+f"(d[0]), "+f"(d[1]), "+f"(d[2]), "+f"(d[3])
        : "r"(a[0]), "r"(a[1]), "r"(a[2]), "r"(a[3]), "r"(b[0]), "r"(b[1]));
}

// ---------------------------------------------------------------------------
// Split: f32 -> (hi bf16, lo bf16)
// ---------------------------------------------------------------------------
__device__ __forceinline__ uint32_t pack2(__nv_bfloat16 a, __nv_bfloat16 b) {
    unsigned short ua = *reinterpret_cast<unsigned short*>(&a);
    unsigned short ub = *reinterpret_cast<unsigned short*>(&b);
    return (uint32_t)ua | ((uint32_t)ub << 16);
}
__global__ __launch_bounds__(256) void split_kernel(
    const float4* __restrict__ in, uint2* __restrict__ hi, uint2* __restrict__ lo, int n4)
{
    int i = blockIdx.x * blockDim.x + threadIdx.x;
    if (i >= n4) return;
    float4 v = in[i];
    __nv_bfloat16 h0 = __float2bfloat16(v.x), h1 = __float2bfloat16(v.y);
    __nv_bfloat16 h2 = __float2bfloat16(v.z), h3 = __float2bfloat16(v.w);
    __nv_bfloat16 l0 = __float2bfloat16(v.x - __bfloat162float(h0));
    __nv_bfloat16 l1 = __float2bfloat16(v.y - __bfloat162float(h1));
    __nv_bfloat16 l2 = __float2bfloat16(v.z - __bfloat162float(h2));
    __nv_bfloat16 l3 = __float2bfloat16(v.w - __bfloat162float(h3));
    uint2 H; H.x = pack2(h0, h1); H.y = pack2(h2, h3);
    uint2 L; L.x = pack2(l0, l1); L.y = pack2(l2, l3);
    hi[i] = H; lo[i] = L;
}

// ---------------------------------------------------------------------------
// HMMA bf16-split GEMM: C[M,2048] = A[M,2048] @ B[2048,2048]^T (fp32)
// CTA tile 128x128, BK=32, 8 warps (2x4), warp tile 64x32.
// smem per stage: 4 matrices (Ah,Al,Bh,Bl) of 128 rows x 32 bf16,
// padded row stride 40 bf16 (80B) -> conflict-free ldmatrix.
// ---------------------------------------------------------------------------
#define BK 32
#define RSTRIDE_B 80                 // bytes per padded row
#define MAT_BYTES (128 * RSTRIDE_B)  // 10240
#define STG_BYTES (4 * MAT_BYTES)    // 40960
#define GEMM_SMEM (2 * STG_BYTES)    // 81920

__global__ __launch_bounds__(256, 1) void gemm_hmma(
    const __nv_bfloat16* __restrict__ Ah, const __nv_bfloat16* __restrict__ Al,
    const __nv_bfloat16* __restrict__ Bh, const __nv_bfloat16* __restrict__ Bl,
    float* __restrict__ C)
{
    extern __shared__ char smem[];
    const uint32_t sbase = smem_u32(smem);
    const int tid  = threadIdx.x;
    const int wid  = tid >> 5;
    const int lane = tid & 31;
    const int row0 = blockIdx.x * 128;
    const int col0 = blockIdx.y * 128;
    const int wm = (wid >> 2) * 64;          // warp M offset within tile
    const int wn = (wid & 3) * 32;           // warp N offset within tile

    float acc[4][4][4];
    #pragma unroll
    for (int mi = 0; mi < 4; ++mi)
        #pragma unroll
        for (int ni = 0; ni < 4; ++ni)
            #pragma unroll
            for (int j = 0; j < 4; ++j) acc[mi][ni][j] = 0.f;

    // ---- stage loader: 2048 x 16B chunks, 8 per thread ----
    auto load_stage = [&](int st, int k0) {
        const uint32_t s = sbase + st * STG_BYTES;
        #pragma unroll
        for (int i = 0; i < 8; ++i) {
            const int mat = i >> 1;                       // 0:Ah 1:Al 2:Bh 3:Bl
            const int rc  = (i & 1) * 256 + tid;          // 0..511
            const int r   = rc >> 2;
            const int c   = rc & 3;
            const __nv_bfloat16* gb;
            int rb;
            if      (mat == 0) { gb = Ah; rb = row0; }
            else if (mat == 1) { gb = Al; rb = row0; }
            else if (mat == 2) { gb = Bh; rb = col0; }
            else               { gb = Bl; rb = col0; }
            cp16(s + mat * MAT_BYTES + r * RSTRIDE_B + c * 16,
                 gb + (size_t)(rb + r) * GK + k0 + c * 8);
        }
        asm volatile("cp.async.commit_group;" ::: "memory");
    };

    load_stage(0, 0);
    load_stage(1, BK);

    const int NCH = GK / BK;                  // 64
    for (int s = 0; s < NCH; ++s) {
        if (s < NCH - 2) asm volatile("cp.async.wait_group 1;" ::: "memory");
        else             asm volatile("cp.async.wait_group 0;" ::: "memory");
        __syncthreads();

        const uint32_t sbuf = sbase + (s & 1) * STG_BYTES;
        #pragma unroll
        for (int kk = 0; kk < BK; kk += 16) {
            uint32_t ah[4][4], al[4][4];
            #pragma unroll
            for (int mi = 0; mi < 4; ++mi) {
                const int arow = wm + mi * 16 + (lane & 15);
                const uint32_t ad = sbuf + arow * RSTRIDE_B + kk * 2 + (lane >> 4) * 16;
                ldsm_x4(ah[mi], ad);
                ldsm_x4(al[mi], ad + MAT_BYTES);
            }
            uint32_t bh[4][2], bl[4][2];
            #pragma unroll
            for (int ni = 0; ni < 4; ++ni) {
                const int brow = wn + ni * 8 + (lane & 7);
                const uint32_t bd = sbuf + 2 * MAT_BYTES + brow * RSTRIDE_B
                                  + kk * 2 + ((lane >> 3) & 1) * 16;
                ldsm_x2(bh[ni], bd);
                ldsm_x2(bl[ni], bd + MAT_BYTES);
            }
            #pragma unroll
            for (int mi = 0; mi < 4; ++mi)
                #pragma unroll
                for (int ni = 0; ni < 4; ++ni) {
                    mma16816(acc[mi][ni], ah[mi], bh[ni]);
                    mma16816(acc[mi][ni], ah[mi], bl[ni]);
                    mma16816(acc[mi][ni], al[mi], bh[ni]);
                }
        }
        __syncthreads();
        if (s + 2 < NCH) load_stage(s & 1, (s + 2) * BK);
    }

    // ---- epilogue: registers -> C ----
    #pragma unroll
    for (int mi = 0; mi < 4; ++mi) {
        const int r0 = row0 + wm + mi * 16 + (lane >> 2);
        #pragma unroll
        for (int ni = 0; ni < 4; ++ni) {
            const int c = col0 + wn + ni * 8 + (lane & 3) * 2;
            float2 v0 = { acc[mi][ni][0], acc[mi][ni][1] };
            float2 v1 = { acc[mi][ni][2], acc[mi][ni][3] };
            *(float2*)(C + (size_t)r0 * GN + c)       = v0;
            *(float2*)(C + (size_t)(r0 + 8) * GN + c) = v1;
        }
    }
}

// ---------------------------------------------------------------------------
// Flash attention (fp32, online softmax) — unchanged from Round 1
// ---------------------------------------------------------------------------
#define BQ   64
#define BKV  64
#define QST  128
#define KVST 132
#define PST  68
#define SM_FLOATS (BQ*QST + BKV*KVST + BKV*KVST + BQ*PST)
#define SM_BYTES  (SM_FLOATS * 4)

__global__ __launch_bounds__(256) void flash_attn(
    const float* __restrict__ Q, const float* __restrict__ K,
    const float* __restrict__ V, float* __restrict__ O)
{
    extern __shared__ float sm[];
    float* Qs = sm;
    float* Ks = Qs + BQ * QST;
    float* Vs = Ks + BKV * KVST;
    float* Ps = Vs + BKV * KVST;

    const int tid = threadIdx.x;
    const int qb  = blockIdx.x;
    const int bh  = blockIdx.y;
    const int b   = bh >> 4;
    const int h   = bh & 15;
    const int q0  = qb * BQ;
    const size_t base = (size_t)b * SEQ * D_MODEL + (size_t)h * DK;

    const float qscale = 0.08838834764831845f;
    for (int i = tid; i < BQ * DK / 4; i += 256) {
        const int r  = i >> 5;
        const int c4 = (i & 31) << 2;
        float4 v = *(const float4*)(Q + base + (size_t)(q0 + r) * D_MODEL + c4);
        v.x *= qscale; v.y *= qscale; v.z *= qscale; v.w *= qscale;
        *(float4*)(Qs + r * QST + c4) = v;
    }

    const int g    = tid >> 4;
    const int cg   = tid & 15;
    const int qr   = g << 2;
    const int dcol = cg << 3;

    float m_i[4], l_i[4], o[4][8];
    #pragma unroll
    for (int i = 0; i < 4; ++i) {
        m_i[i] = -1e30f; l_i[i] = 0.f;
        #pragma unroll
        for (int d = 0; d < 8; ++d) o[i][d] = 0.f;
    }

    for (int kb = 0; kb < SEQ; kb += BKV) {
        __syncthreads();
        for (int i = tid; i < BKV * DK / 4; i += 256) {
            const int r  = i >> 5;
            const int c4 = (i & 31) << 2;
            const size_t goff = base + (size_t)(kb + r) * D_MODEL + c4;
            *(float4*)(Ks + r * KVST + c4) = *(const float4*)(K + goff);
            *(float4*)(Vs + r * KVST + c4) = *(const float4*)(V + goff);
        }
        __syncthreads();

        float s[4][4];
        #pragma unroll
        for (int i = 0; i < 4; ++i)
            #pragma unroll
            for (int j = 0; j < 4; ++j) s[i][j] = 0.f;

        #pragma unroll 4
        for (int d = 0; d < DK; d += 4) {
            float4 qa[4], kv[4];
            #pragma unroll
            for (int i = 0; i < 4; ++i) qa[i] = *(const float4*)&Qs[(qr + i) * QST + d];
            #pragma unroll
            for (int j = 0; j < 4; ++j) kv[j] = *(const float4*)&Ks[(cg * 4 + j) * KVST + d];
            #pragma unroll
            for (int i = 0; i < 4; ++i)
                #pragma unroll
                for (int j = 0; j < 4; ++j)
                    s[i][j] += qa[i].x * kv[j].x + qa[i].y * kv[j].y
                             + qa[i].z * kv[j].z + qa[i].w * kv[j].w;
        }

        float alpha[4];
        #pragma unroll
        for (int i = 0; i < 4; ++i) {
            float mx = fmaxf(fmaxf(s[i][0], s[i][1]), fmaxf(s[i][2], s[i][3]));
            #pragma unroll
            for (int off = 1; off < 16; off <<= 1)
                mx = fmaxf(mx, __shfl_xor_sync(0xffffffffu, mx, off));
            const float mnew = fmaxf(m_i[i], mx);
            float lsum = 0.f;
            #pragma unroll
            for (int j = 0; j < 4; ++j) {
                const float p = __expf(s[i][j] - mnew);
                Ps[(qr + i) * PST + cg * 4 + j] = p;
                lsum += p;
            }
            #pragma unroll
            for (int off = 1; off < 16; off <<= 1)
                lsum += __shfl_xor_sync(0xffffffffu, lsum, off);
            alpha[i] = __expf(m_i[i] - mnew);
            l_i[i] = l_i[i] * alpha[i] + lsum;
            m_i[i] = mnew;
        }
        __syncthreads();

        #pragma unroll
        for (int i = 0; i < 4; ++i)
            #pragma unroll
            for (int d = 0; d < 8; ++d) o[i][d] *= alpha[i];

        #pragma unroll 2
        for (int j = 0; j < BKV; j += 4) {
            float pr[4][4];
            #pragma unroll
            for (int i = 0; i < 4; ++i) {
                const float4 pv = *(const float4*)&Ps[(qr + i) * PST + j];
                pr[i][0] = pv.x; pr[i][1] = pv.y; pr[i][2] = pv.z; pr[i][3] = pv.w;
            }
            #pragma unroll
            for (int jj = 0; jj < 4; ++jj) {
                const float4 v0 = *(const float4*)&Vs[(j + jj) * KVST + dcol];
                const float4 v1 = *(const float4*)&Vs[(j + jj) * KVST + dcol + 4];
                const float vr[8] = {v0.x, v0.y, v0.z, v0.w, v1.x, v1.y, v1.z, v1.w};
                #pragma unroll
                for (int i = 0; i < 4; ++i)
                    #pragma unroll
                    for (int d = 0; d < 8; ++d)
                        o[i][d] += pr[i][jj] * vr[d];
            }
        }
    }

    #pragma unroll
    for (int i = 0; i < 4; ++i) {
        const float rl = 1.f / l_i[i];
        float4 u0 = {o[i][0] * rl, o[i][1] * rl, o[i][2] * rl, o[i][3] * rl};
        float4 u1 = {o[i][4] * rl, o[i][5] * rl, o[i][6] * rl, o[i][7] * rl};
        float* op = O + base + (size_t)(q0 + qr + i) * D_MODEL + dcol;
        *(float4*)(op)     = u0;
        *(float4*)(op + 4) = u1;
    }
}

// ---------------------------------------------------------------------------
// Launch
// ---------------------------------------------------------------------------
extern "C" void kernel_launch(void* const* d_in, const int* in_sizes, int n_in,
                              void* d_out, int out_size)
{
    const float* x  = (const float*)d_in[0];
    const float* wq = (const float*)d_in[1];
    const float* wk = (const float*)d_in[2];
    const float* wv = (const float*)d_in[3];
    const float* wo = (const float*)d_in[4];
    float* out = (float*)d_out;

    float *Q, *K, *V, *C;
    cudaGetSymbolAddress((void**)&Q, g_Q);
    cudaGetSymbolAddress((void**)&K, g_K);
    cudaGetSymbolAddress((void**)&V, g_V);
    cudaGetSymbolAddress((void**)&C, g_C);
    __nv_bfloat16 *xh, *xl, *ch, *cl, *wqh, *wql, *wkh, *wkl, *wvh, *wvl, *woh, *wol;
    cudaGetSymbolAddress((void**)&xh, g_xh);   cudaGetSymbolAddress((void**)&xl, g_xl);
    cudaGetSymbolAddress((void**)&ch, g_ch);   cudaGetSymbolAddress((void**)&cl, g_cl);
    cudaGetSymbolAddress((void**)&wqh, g_wqh); cudaGetSymbolAddress((void**)&wql, g_wql);
    cudaGetSymbolAddress((void**)&wkh, g_wkh); cudaGetSymbolAddress((void**)&wkl, g_wkl);
    cudaGetSymbolAddress((void**)&wvh, g_wvh); cudaGetSymbolAddress((void**)&wvl, g_wvl);
    cudaGetSymbolAddress((void**)&woh, g_woh); cudaGetSymbolAddress((void**)&wol, g_wol);

    cudaFuncSetAttribute(gemm_hmma, cudaFuncAttributeMaxDynamicSharedMemorySize, GEMM_SMEM);
    cudaFuncSetAttribute(flash_attn, cudaFuncAttributeMaxDynamicSharedMemorySize, SM_BYTES);

    const int n4x = (M_TOT * D_MODEL) / 4;
    const int n4w = (D_MODEL * D_MODEL) / 4;

    split_kernel<<<n4x / 256, 256>>>((const float4*)x,  (uint2*)xh,  (uint2*)xl,  n4x);
    split_kernel<<<n4w / 256, 256>>>((const float4*)wq, (uint2*)wqh, (uint2*)wql, n4w);
    split_kernel<<<n4w / 256, 256>>>((const float4*)wk, (uint2*)wkh, (uint2*)wkl, n4w);
    split_kernel<<<n4w / 256, 256>>>((const float4*)wv, (uint2*)wvh, (uint2*)wvl, n4w);
    split_kernel<<<n4w / 256, 256>>>((const float4*)wo, (uint2*)woh, (uint2*)wol, n4w);

    const dim3 gg(M_TOT / 128, GN / 128);    // (64, 16)
    gemm_hmma<<<gg, 256, GEMM_SMEM>>>(xh, xl, wqh, wql, Q);
    gemm_hmma<<<gg, 256, GEMM_SMEM>>>(xh, xl, wkh, wkl, K);
    gemm_hmma<<<gg, 256, GEMM_SMEM>>>(xh, xl, wvh, wvl, V);

    flash_attn<<<dim3(SEQ / BQ, BATCH * NHEAD), 256, SM_BYTES>>>(Q, K, V, C);

    split_kernel<<<n4x / 256, 256>>>((const float4*)C, (uint2*)ch, (uint2*)cl, n4x);
    gemm_hmma<<<gg, 256, GEMM_SMEM>>>(ch, cl, woh, wol, out);
}

// round 4
// speedup vs baseline: 1.3287x; 1.0069x over previous
#include <cuda_runtime.h>
#include <cuda_bf16.h>
#include <cstdint>
#include <math.h>

// ---------------------------------------------------------------------------
// Problem constants
// ---------------------------------------------------------------------------
#define D_MODEL 2048
#define SEQ     2048
#define BATCH   4
#define NHEAD   16
#define DK      128
#define M_TOT   (BATCH * SEQ)       // 8192
#define GK      2048
#define GN      2048

// ---------------------------------------------------------------------------
// Scratch (allocation-free rule: __device__ globals)
// ---------------------------------------------------------------------------
__device__ float g_Q[(size_t)M_TOT * D_MODEL];
__device__ float g_K[(size_t)M_TOT * D_MODEL];
__device__ float g_V[(size_t)M_TOT * D_MODEL];
__device__ float g_C[(size_t)M_TOT * D_MODEL];

__device__ __nv_bfloat16 g_xh[(size_t)M_TOT * D_MODEL];
__device__ __nv_bfloat16 g_xl[(size_t)M_TOT * D_MODEL];
__device__ __nv_bfloat16 g_ch[(size_t)M_TOT * D_MODEL];
__device__ __nv_bfloat16 g_cl[(size_t)M_TOT * D_MODEL];
__device__ __nv_bfloat16 g_wqh[(size_t)D_MODEL * D_MODEL];
__device__ __nv_bfloat16 g_wql[(size_t)D_MODEL * D_MODEL];
__device__ __nv_bfloat16 g_wkh[(size_t)D_MODEL * D_MODEL];
__device__ __nv_bfloat16 g_wkl[(size_t)D_MODEL * D_MODEL];
__device__ __nv_bfloat16 g_wvh[(size_t)D_MODEL * D_MODEL];
__device__ __nv_bfloat16 g_wvl[(size_t)D_MODEL * D_MODEL];
__device__ __nv_bfloat16 g_woh[(size_t)D_MODEL * D_MODEL];
__device__ __nv_bfloat16 g_wol[(size_t)D_MODEL * D_MODEL];

// ---------------------------------------------------------------------------
// Helpers
// ---------------------------------------------------------------------------
__device__ __forceinline__ uint32_t smem_u32(const void* p) {
    uint32_t a;
    asm("{ .reg .u64 t; cvta.to.shared.u64 t, %1; cvt.u32.u64 %0, t; }" : "=r"(a) : "l"(p));
    return a;
}
__device__ __forceinline__ void cp16(uint32_t s, const void* g) {
    asm volatile("cp.async.cg.shared.global [%0], [%1], 16;" :: "r"(s), "l"(g));
}
__device__ __forceinline__ void ldsm_x4(uint32_t (&r)[4], uint32_t addr) {
    asm volatile("ldmatrix.sync.aligned.m8n8.x4.shared.b16 {%0,%1,%2,%3}, [%4];"
        : "=r"(r[0]), "=r"(r[1]), "=r"(r[2]), "=r"(r[3]) : "r"(addr));
}
__device__ __forceinline__ void mma16816(float (&d)[4], const uint32_t (&a)[4],
                                         const uint32_t* b) {
    asm volatile("mma.sync.aligned.m16n8k16.row.col.f32.bf16.bf16.f32 "
        "{%0,%1,%2,%3}, {%4,%5,%6,%7}, {%8,%9}, {%0,%1,%2,%3};"
        : "+f"(d[0]), "+f"(d[1]), "+f"(d[2]), "+f"(d[3])
        : "r"(a[0]), "r"(a[1]), "r"(a[2]), "r"(a[3]), "r"(b[0]), "r"(b[1]));
}

// ---------------------------------------------------------------------------
// Split: f32 -> (hi bf16, lo bf16)
// ---------------------------------------------------------------------------
__device__ __forceinline__ uint32_t pack2(__nv_bfloat16 a, __nv_bfloat16 b) {
    unsigned short ua = *reinterpret_cast<unsigned short*>(&a);
    unsigned short ub = *reinterpret_cast<unsigned short*>(&b);
    return (uint32_t)ua | ((uint32_t)ub << 16);
}
__global__ __launch_bounds__(256) void split_kernel(
    const float4* __restrict__ in, uint2* __restrict__ hi, uint2* __restrict__ lo, int n4)
{
    int i = blockIdx.x * blockDim.x + threadIdx.x;
    if (i >= n4) return;
    float4 v = in[i];
    __nv_bfloat16 h0 = __float2bfloat16(v.x), h1 = __float2bfloat16(v.y);
    __nv_bfloat16 h2 = __float2bfloat16(v.z), h3 = __float2bfloat16(v.w);
    __nv_bfloat16 l0 = __float2bfloat16(v.x - __bfloat162float(h0));
    __nv_bfloat16 l1 = __float2bfloat16(v.y - __bfloat162float(h1));
    __nv_bfloat16 l2 = __float2bfloat16(v.z - __bfloat162float(h2));
    __nv_bfloat16 l3 = __float2bfloat16(v.w - __bfloat162float(h3));
    uint2 H; H.x = pack2(h0, h1); H.y = pack2(h2, h3);
    uint2 L; L.x = pack2(l0, l1); L.y = pack2(l2, l3);
    hi[i] = H; lo[i] = L;
}

// ---------------------------------------------------------------------------
// HMMA bf16-split GEMM: C[M,2048] = A[M,2048] @ B[2048,2048]^T (fp32)
// CTA tile 128x128, BK=32, 8 warps (2x4), warp tile 64x32.
// 4-stage cp.async pipeline, prefetch distance 3.
// ---------------------------------------------------------------------------
#define BK 32
#define RSTRIDE_B 80                 // bytes per padded row (32 bf16 + 8 pad)
#define MAT_BYTES (128 * RSTRIDE_B)  // 10240
#define STG_BYTES (4 * MAT_BYTES)    // 40960
#define NSTAGE 4
#define GEMM_SMEM (NSTAGE * STG_BYTES)  // 163840

__global__ __launch_bounds__(256, 1) void gemm_hmma(
    const __nv_bfloat16* __restrict__ Ah, const __nv_bfloat16* __restrict__ Al,
    const __nv_bfloat16* __restrict__ Bh, const __nv_bfloat16* __restrict__ Bl,
    float* __restrict__ C)
{
    extern __shared__ char smem[];
    const uint32_t sbase = smem_u32(smem);
    const int tid  = threadIdx.x;
    const int wid  = tid >> 5;
    const int lane = tid & 31;
    const int row0 = blockIdx.x * 128;
    const int col0 = blockIdx.y * 128;
    const int wm = (wid >> 2) * 64;          // warp M offset within tile
    const int wn = (wid & 3) * 32;           // warp N offset within tile

    float acc[4][4][4];
    #pragma unroll
    for (int mi = 0; mi < 4; ++mi)
        #pragma unroll
        for (int ni = 0; ni < 4; ++ni)
            #pragma unroll
            for (int j = 0; j < 4; ++j) acc[mi][ni][j] = 0.f;

    // ---- stage loader: 2048 x 16B chunks, 8 per thread ----
    auto load_stage = [&](int st, int k0) {
        const uint32_t s = sbase + st * STG_BYTES;
        #pragma unroll
        for (int i = 0; i < 8; ++i) {
            const int mat = i >> 1;                       // 0:Ah 1:Al 2:Bh 3:Bl
            const int rc  = (i & 1) * 256 + tid;          // 0..511
            const int r   = rc >> 2;
            const int c   = rc & 3;
            const __nv_bfloat16* gb;
            int rb;
            if      (mat == 0) { gb = Ah; rb = row0; }
            else if (mat == 1) { gb = Al; rb = row0; }
            else if (mat == 2) { gb = Bh; rb = col0; }
            else               { gb = Bl; rb = col0; }
            cp16(s + mat * MAT_BYTES + r * RSTRIDE_B + c * 16,
                 gb + (size_t)(rb + r) * GK + k0 + c * 8);
        }
        asm volatile("cp.async.commit_group;" ::: "memory");
    };

    load_stage(0, 0);
    load_stage(1, BK);
    load_stage(2, 2 * BK);

    const int NCH = GK / BK;                  // 64
    for (int s = 0; s < NCH; ++s) {
        if (s < NCH - 2)      asm volatile("cp.async.wait_group 2;" ::: "memory");
        else if (s == NCH-2)  asm volatile("cp.async.wait_group 1;" ::: "memory");
        else                  asm volatile("cp.async.wait_group 0;" ::: "memory");
        __syncthreads();

        // issue next stage's loads FIRST so they overlap the whole MMA phase
        if (s + 3 < NCH) load_stage((s + 3) & (NSTAGE - 1), (s + 3) * BK);

        const uint32_t sbuf = sbase + (s & (NSTAGE - 1)) * STG_BYTES;
        #pragma unroll
        for (int kk = 0; kk < 2; ++kk) {      // two k16 steps per BK=32
            uint32_t ah[4][4], al[4][4];
            #pragma unroll
            for (int mi = 0; mi < 4; ++mi) {
                const int arow = wm + mi * 16 + (lane & 15);
                const uint32_t ad = sbuf + arow * RSTRIDE_B + kk * 32 + (lane >> 4) * 16;
                ldsm_x4(ah[mi], ad);
                ldsm_x4(al[mi], ad + MAT_BYTES);
            }
            uint32_t bh[4][4], bl[4][4];      // [pair][4 regs] = 2 n8 frags each
            #pragma unroll
            for (int p = 0; p < 2; ++p) {
                const int brow = wn + p * 16 + (lane & 7) + ((lane >> 4) << 3);
                const uint32_t bd = sbuf + 2 * MAT_BYTES + brow * RSTRIDE_B
                                  + kk * 32 + (((lane >> 3) & 1) << 4);
                ldsm_x4(bh[p], bd);
                ldsm_x4(bl[p], bd + MAT_BYTES);
            }
            #pragma unroll
            for (int mi = 0; mi < 4; ++mi)
                #pragma unroll
                for (int ni = 0; ni < 4; ++ni) {
                    const uint32_t* bhf = &bh[ni >> 1][(ni & 1) * 2];
                    const uint32_t* blf = &bl[ni >> 1][(ni & 1) * 2];
                    mma16816(acc[mi][ni], ah[mi], bhf);
                    mma16816(acc[mi][ni], ah[mi], blf);
                    mma16816(acc[mi][ni], al[mi], bhf);
                }
        }
    }

    // ---- epilogue: registers -> C ----
    #pragma unroll
    for (int mi = 0; mi < 4; ++mi) {
        const int r0 = row0 + wm + mi * 16 + (lane >> 2);
        #pragma unroll
        for (int ni = 0; ni < 4; ++ni) {
            const int c = col0 + wn + ni * 8 + (lane & 3) * 2;
            float2 v0 = { acc[mi][ni][0], acc[mi][ni][1] };
            float2 v1 = { acc[mi][ni][2], acc[mi][ni][3] };
            *(float2*)(C + (size_t)r0 * GN + c)       = v0;
            *(float2*)(C + (size_t)(r0 + 8) * GN + c) = v1;
        }
    }
}

// ---------------------------------------------------------------------------
// Flash attention (fp32, online softmax) — unchanged
// ---------------------------------------------------------------------------
#define BQ   64
#define BKV  64
#define QST  128
#define KVST 132
#define PST  68
#define SM_FLOATS (BQ*QST + BKV*KVST + BKV*KVST + BQ*PST)
#define SM_BYTES  (SM_FLOATS * 4)

__global__ __launch_bounds__(256) void flash_attn(
    const float* __restrict__ Q, const float* __restrict__ K,
    const float* __restrict__ V, float* __restrict__ O)
{
    extern __shared__ float sm[];
    float* Qs = sm;
    float* Ks = Qs + BQ * QST;
    float* Vs = Ks + BKV * KVST;
    float* Ps = Vs + BKV * KVST;

    const int tid = threadIdx.x;
    const int qb  = blockIdx.x;
    const int bh  = blockIdx.y;
    const int b   = bh >> 4;
    const int h   = bh & 15;
    const int q0  = qb * BQ;
    const size_t base = (size_t)b * SEQ * D_MODEL + (size_t)h * DK;

    const float qscale = 0.08838834764831845f;
    for (int i = tid; i < BQ * DK / 4; i += 256) {
        const int r  = i >> 5;
        const int c4 = (i & 31) << 2;
        float4 v = *(const float4*)(Q + base + (size_t)(q0 + r) * D_MODEL + c4);
        v.x *= qscale; v.y *= qscale; v.z *= qscale; v.w *= qscale;
        *(float4*)(Qs + r * QST + c4) = v;
    }

    const int g    = tid >> 4;
    const int cg   = tid & 15;
    const int qr   = g << 2;
    const int dcol = cg << 3;

    float m_i[4], l_i[4], o[4][8];
    #pragma unroll
    for (int i = 0; i < 4; ++i) {
        m_i[i] = -1e30f; l_i[i] = 0.f;
        #pragma unroll
        for (int d = 0; d < 8; ++d) o[i][d] = 0.f;
    }

    for (int kb = 0; kb < SEQ; kb += BKV) {
        __syncthreads();
        for (int i = tid; i < BKV * DK / 4; i += 256) {
            const int r  = i >> 5;
            const int c4 = (i & 31) << 2;
            const size_t goff = base + (size_t)(kb + r) * D_MODEL + c4;
            *(float4*)(Ks + r * KVST + c4) = *(const float4*)(K + goff);
            *(float4*)(Vs + r * KVST + c4) = *(const float4*)(V + goff);
        }
        __syncthreads();

        float s[4][4];
        #pragma unroll
        for (int i = 0; i < 4; ++i)
            #pragma unroll
            for (int j = 0; j < 4; ++j) s[i][j] = 0.f;

        #pragma unroll 4
        for (int d = 0; d < DK; d += 4) {
            float4 qa[4], kv[4];
            #pragma unroll
            for (int i = 0; i < 4; ++i) qa[i] = *(const float4*)&Qs[(qr + i) * QST + d];
            #pragma unroll
            for (int j = 0; j < 4; ++j) kv[j] = *(const float4*)&Ks[(cg * 4 + j) * KVST + d];
            #pragma unroll
            for (int i = 0; i < 4; ++i)
                #pragma unroll
                for (int j = 0; j < 4; ++j)
                    s[i][j] += qa[i].x * kv[j].x + qa[i].y * kv[j].y
                             + qa[i].z * kv[j].z + qa[i].w * kv[j].w;
        }

        float alpha[4];
        #pragma unroll
        for (int i = 0; i < 4; ++i) {
            float mx = fmaxf(fmaxf(s[i][0], s[i][1]), fmaxf(s[i][2], s[i][3]));
            #pragma unroll
            for (int off = 1; off < 16; off <<= 1)
                mx = fmaxf(mx, __shfl_xor_sync(0xffffffffu, mx, off));
            const float mnew = fmaxf(m_i[i], mx);
            float lsum = 0.f;
            #pragma unroll
            for (int j = 0; j < 4; ++j) {
                const float p = __expf(s[i][j] - mnew);
                Ps[(qr + i) * PST + cg * 4 + j] = p;
                lsum += p;
            }
            #pragma unroll
            for (int off = 1; off < 16; off <<= 1)
                lsum += __shfl_xor_sync(0xffffffffu, lsum, off);
            alpha[i] = __expf(m_i[i] - mnew);
            l_i[i] = l_i[i] * alpha[i] + lsum;
            m_i[i] = mnew;
        }
        __syncthreads();

        #pragma unroll
        for (int i = 0; i < 4; ++i)
            #pragma unroll
            for (int d = 0; d < 8; ++d) o[i][d] *= alpha[i];

        #pragma unroll 2
        for (int j = 0; j < BKV; j += 4) {
            float pr[4][4];
            #pragma unroll
            for (int i = 0; i < 4; ++i) {
                const float4 pv = *(const float4*)&Ps[(qr + i) * PST + j];
                pr[i][0] = pv.x; pr[i][1] = pv.y; pr[i][2] = pv.z; pr[i][3] = pv.w;
            }
            #pragma unroll
            for (int jj = 0; jj < 4; ++jj) {
                const float4 v0 = *(const float4*)&Vs[(j + jj) * KVST + dcol];
                const float4 v1 = *(const float4*)&Vs[(j + jj) * KVST + dcol + 4];
                const float vr[8] = {v0.x, v0.y, v0.z, v0.w, v1.x, v1.y, v1.z, v1.w};
                #pragma unroll
                for (int i = 0; i < 4; ++i)
                    #pragma unroll
                    for (int d = 0; d < 8; ++d)
                        o[i][d] += pr[i][jj] * vr[d];
            }
        }
    }

    #pragma unroll
    for (int i = 0; i < 4; ++i) {
        const float rl = 1.f / l_i[i];
        float4 u0 = {o[i][0] * rl, o[i][1] * rl, o[i][2] * rl, o[i][3] * rl};
        float4 u1 = {o[i][4] * rl, o[i][5] * rl, o[i][6] * rl, o[i][7] * rl};
        float* op = O + base + (size_t)(q0 + qr + i) * D_MODEL + dcol;
        *(float4*)(op)     = u0;
        *(float4*)(op + 4) = u1;
    }
}

// ---------------------------------------------------------------------------
// Launch
// ---------------------------------------------------------------------------
extern "C" void kernel_launch(void* const* d_in, const int* in_sizes, int n_in,
                              void* d_out, int out_size)
{
    const float* x  = (const float*)d_in[0];
    const float* wq = (const float*)d_in[1];
    const float* wk = (const float*)d_in[2];
    const float* wv = (const float*)d_in[3];
    const float* wo = (const float*)d_in[4];
    float* out = (float*)d_out;

    float *Q, *K, *V, *C;
    cudaGetSymbolAddress((void**)&Q, g_Q);
    cudaGetSymbolAddress((void**)&K, g_K);
    cudaGetSymbolAddress((void**)&V, g_V);
    cudaGetSymbolAddress((void**)&C, g_C);
    __nv_bfloat16 *xh, *xl, *ch, *cl, *wqh, *wql, *wkh, *wkl, *wvh, *wvl, *woh, *wol;
    cudaGetSymbolAddress((void**)&xh, g_xh);   cudaGetSymbolAddress((void**)&xl, g_xl);
    cudaGetSymbolAddress((void**)&ch, g_ch);   cudaGetSymbolAddress((void**)&cl, g_cl);
    cudaGetSymbolAddress((void**)&wqh, g_wqh); cudaGetSymbolAddress((void**)&wql, g_wql);
    cudaGetSymbolAddress((void**)&wkh, g_wkh); cudaGetSymbolAddress((void**)&wkl, g_wkl);
    cudaGetSymbolAddress((void**)&wvh, g_wvh); cudaGetSymbolAddress((void**)&wvl, g_wvl);
    cudaGetSymbolAddress((void**)&woh, g_woh); cudaGetSymbolAddress((void**)&wol, g_wol);

    cudaFuncSetAttribute(gemm_hmma, cudaFuncAttributeMaxDynamicSharedMemorySize, GEMM_SMEM);
    cudaFuncSetAttribute(flash_attn, cudaFuncAttributeMaxDynamicSharedMemorySize, SM_BYTES);

    const int n4x = (M_TOT * D_MODEL) / 4;
    const int n4w = (D_MODEL * D_MODEL) / 4;

    split_kernel<<<n4x / 256, 256>>>((const float4*)x,  (uint2*)xh,  (uint2*)xl,  n4x);
    split_kernel<<<n4w / 256, 256>>>((const float4*)wq, (uint2*)wqh, (uint2*)wql, n4w);
    split_kernel<<<n4w / 256, 256>>>((const float4*)wk, (uint2*)wkh, (uint2*)wkl, n4w);
    split_kernel<<<n4w / 256, 256>>>((const float4*)wv, (uint2*)wvh, (uint2*)wvl, n4w);
    split_kernel<<<n4w / 256, 256>>>((const float4*)wo, (uint2*)woh, (uint2*)wol, n4w);

    const dim3 gg(M_TOT / 128, GN / 128);    // (64, 16)
    gemm_hmma<<<gg, 256, GEMM_SMEM>>>(xh, xl, wqh, wql, Q);
    gemm_hmma<<<gg, 256, GEMM_SMEM>>>(xh, xl, wkh, wkl, K);
    gemm_hmma<<<gg, 256, GEMM_SMEM>>>(xh, xl, wvh, wvl, V);

    flash_attn<<<dim3(SEQ / BQ, BATCH * NHEAD), 256, SM_BYTES>>>(Q, K, V, C);

    split_kernel<<<n4x / 256, 256>>>((const float4*)C, (uint2*)ch, (uint2*)cl, n4x);
    gemm_hmma<<<gg, 256, GEMM_SMEM>>>(ch, cl, woh, wol, out);
}

// round 5
// speedup vs baseline: 3.5858x; 2.6986x over previous
#include <cuda_runtime.h>
#include <cuda_bf16.h>
#include <cstdint>
#include <math.h>

// ---------------------------------------------------------------------------
// Problem constants
// ---------------------------------------------------------------------------
#define D_MODEL 2048
#define SEQ     2048
#define BATCH   4
#define NHEAD   16
#define DK      128
#define M_TOT   (BATCH * SEQ)       // 8192
#define GK      2048
#define GN      2048

// ---------------------------------------------------------------------------
// Scratch (allocation-free rule: __device__ globals)  — all bf16 hi/lo pairs
// ---------------------------------------------------------------------------
__device__ __nv_bfloat16 g_Qh[(size_t)M_TOT * D_MODEL];
__device__ __nv_bfloat16 g_Ql[(size_t)M_TOT * D_MODEL];
__device__ __nv_bfloat16 g_Kh[(size_t)M_TOT * D_MODEL];
__device__ __nv_bfloat16 g_Kl[(size_t)M_TOT * D_MODEL];
__device__ __nv_bfloat16 g_Vh[(size_t)M_TOT * D_MODEL];
__device__ __nv_bfloat16 g_Vl[(size_t)M_TOT * D_MODEL];
__device__ __nv_bfloat16 g_ch[(size_t)M_TOT * D_MODEL];
__device__ __nv_bfloat16 g_cl[(size_t)M_TOT * D_MODEL];

__device__ __nv_bfloat16 g_xh[(size_t)M_TOT * D_MODEL];
__device__ __nv_bfloat16 g_xl[(size_t)M_TOT * D_MODEL];
__device__ __nv_bfloat16 g_wqh[(size_t)D_MODEL * D_MODEL];
__device__ __nv_bfloat16 g_wql[(size_t)D_MODEL * D_MODEL];
__device__ __nv_bfloat16 g_wkh[(size_t)D_MODEL * D_MODEL];
__device__ __nv_bfloat16 g_wkl[(size_t)D_MODEL * D_MODEL];
__device__ __nv_bfloat16 g_wvh[(size_t)D_MODEL * D_MODEL];
__device__ __nv_bfloat16 g_wvl[(size_t)D_MODEL * D_MODEL];
__device__ __nv_bfloat16 g_woh[(size_t)D_MODEL * D_MODEL];
__device__ __nv_bfloat16 g_wol[(size_t)D_MODEL * D_MODEL];

#define QSCALE 0.08838834764831845f

// ---------------------------------------------------------------------------
// Helpers
// ---------------------------------------------------------------------------
__device__ __forceinline__ uint32_t smem_u32(const void* p) {
    uint32_t a;
    asm("{ .reg .u64 t; cvta.to.shared.u64 t, %1; cvt.u32.u64 %0, t; }" : "=r"(a) : "l"(p));
    return a;
}
__device__ __forceinline__ void cp16(uint32_t s, const void* g) {
    asm volatile("cp.async.cg.shared.global [%0], [%1], 16;" :: "r"(s), "l"(g));
}
__device__ __forceinline__ void ldsm_x4(uint32_t (&r)[4], uint32_t addr) {
    asm volatile("ldmatrix.sync.aligned.m8n8.x4.shared.b16 {%0,%1,%2,%3}, [%4];"
        : "=r"(r[0]), "=r"(r[1]), "=r"(r[2]), "=r"(r[3]) : "r"(addr));
}
__device__ __forceinline__ void ldsm_x4_t(uint32_t (&r)[4], uint32_t addr) {
    asm volatile("ldmatrix.sync.aligned.m8n8.x4.trans.shared.b16 {%0,%1,%2,%3}, [%4];"
        : "=r"(r[0]), "=r"(r[1]), "=r"(r[2]), "=r"(r[3]) : "r"(addr));
}
__device__ __forceinline__ void mma16816(float (&d)[4], const uint32_t (&a)[4],
                                         const uint32_t* b) {
    asm volatile("mma.sync.aligned.m16n8k16.row.col.f32.bf16.bf16.f32 "
        "{%0,%1,%2,%3}, {%4,%5,%6,%7}, {%8,%9}, {%0,%1,%2,%3};"
        : "+f"(d[0]), "+f"(d[1]), "+f"(d[2]), "+f"(d[3])
        : "r"(a[0]), "r"(a[1]), "r"(a[2]), "r"(a[3]), "r"(b[0]), "r"(b[1]));
}
__device__ __forceinline__ uint32_t pack2(__nv_bfloat16 a, __nv_bfloat16 b) {
    unsigned short ua = *reinterpret_cast<unsigned short*>(&a);
    unsigned short ub = *reinterpret_cast<unsigned short*>(&b);
    return (uint32_t)ua | ((uint32_t)ub << 16);
}

// ---------------------------------------------------------------------------
// Split: f32 -> (hi bf16, lo bf16)
// ---------------------------------------------------------------------------
__global__ __launch_bounds__(256) void split_kernel(
    const float4* __restrict__ in, uint2* __restrict__ hi, uint2* __restrict__ lo, int n4)
{
    int i = blockIdx.x * blockDim.x + threadIdx.x;
    if (i >= n4) return;
    float4 v = in[i];
    __nv_bfloat16 h0 = __float2bfloat16(v.x), h1 = __float2bfloat16(v.y);
    __nv_bfloat16 h2 = __float2bfloat16(v.z), h3 = __float2bfloat16(v.w);
    __nv_bfloat16 l0 = __float2bfloat16(v.x - __bfloat162float(h0));
    __nv_bfloat16 l1 = __float2bfloat16(v.y - __bfloat162float(h1));
    __nv_bfloat16 l2 = __float2bfloat16(v.z - __bfloat162float(h2));
    __nv_bfloat16 l3 = __float2bfloat16(v.w - __bfloat162float(h3));
    uint2 H; H.x = pack2(h0, h1); H.y = pack2(h2, h3);
    uint2 L; L.x = pack2(l0, l1); L.y = pack2(l2, l3);
    hi[i] = H; lo[i] = L;
}

// ---------------------------------------------------------------------------
// HMMA bf16-split GEMM: C = A @ B^T, A,B hi/lo bf16.
// SPLIT=true: write bf16 hi/lo output (scaled); SPLIT=false: write f32.
// CTA tile 128x128, BK=32, 8 warps, 4-stage cp.async pipeline.
// ---------------------------------------------------------------------------
#define BK 32
#define RSTRIDE_B 80
#define MAT_BYTES (128 * RSTRIDE_B)
#define STG_BYTES (4 * MAT_BYTES)
#define NSTAGE 4
#define GEMM_SMEM (NSTAGE * STG_BYTES)

template<bool SPLIT>
__global__ __launch_bounds__(256, 1) void gemm_hmma(
    const __nv_bfloat16* __restrict__ Ah, const __nv_bfloat16* __restrict__ Al,
    const __nv_bfloat16* __restrict__ Bh, const __nv_bfloat16* __restrict__ Bl,
    float* __restrict__ C, __nv_bfloat16* __restrict__ Ch,
    __nv_bfloat16* __restrict__ Cl, float scale)
{
    extern __shared__ char smem[];
    const uint32_t sbase = smem_u32(smem);
    const int tid  = threadIdx.x;
    const int wid  = tid >> 5;
    const int lane = tid & 31;
    const int row0 = blockIdx.x * 128;
    const int col0 = blockIdx.y * 128;
    const int wm = (wid >> 2) * 64;
    const int wn = (wid & 3) * 32;

    float acc[4][4][4];
    #pragma unroll
    for (int mi = 0; mi < 4; ++mi)
        #pragma unroll
        for (int ni = 0; ni < 4; ++ni)
            #pragma unroll
            for (int j = 0; j < 4; ++j) acc[mi][ni][j] = 0.f;

    auto load_stage = [&](int st, int k0) {
        const uint32_t s = sbase + st * STG_BYTES;
        #pragma unroll
        for (int i = 0; i < 8; ++i) {
            const int mat = i >> 1;
            const int rc  = (i & 1) * 256 + tid;
            const int r   = rc >> 2;
            const int c   = rc & 3;
            const __nv_bfloat16* gb;
            int rb;
            if      (mat == 0) { gb = Ah; rb = row0; }
            else if (mat == 1) { gb = Al; rb = row0; }
            else if (mat == 2) { gb = Bh; rb = col0; }
            else               { gb = Bl; rb = col0; }
            cp16(s + mat * MAT_BYTES + r * RSTRIDE_B + c * 16,
                 gb + (size_t)(rb + r) * GK + k0 + c * 8);
        }
        asm volatile("cp.async.commit_group;" ::: "memory");
    };

    load_stage(0, 0);
    load_stage(1, BK);
    load_stage(2, 2 * BK);

    const int NCH = GK / BK;
    for (int s = 0; s < NCH; ++s) {
        if (s < NCH - 2)      asm volatile("cp.async.wait_group 2;" ::: "memory");
        else if (s == NCH-2)  asm volatile("cp.async.wait_group 1;" ::: "memory");
        else                  asm volatile("cp.async.wait_group 0;" ::: "memory");
        __syncthreads();
        if (s + 3 < NCH) load_stage((s + 3) & (NSTAGE - 1), (s + 3) * BK);

        const uint32_t sbuf = sbase + (s & (NSTAGE - 1)) * STG_BYTES;
        #pragma unroll
        for (int kk = 0; kk < 2; ++kk) {
            uint32_t ah[4][4], al[4][4];
            #pragma unroll
            for (int mi = 0; mi < 4; ++mi) {
                const int arow = wm + mi * 16 + (lane & 15);
                const uint32_t ad = sbuf + arow * RSTRIDE_B + kk * 32 + (lane >> 4) * 16;
                ldsm_x4(ah[mi], ad);
                ldsm_x4(al[mi], ad + MAT_BYTES);
            }
            uint32_t bh[2][4], bl[2][4];
            #pragma unroll
            for (int p = 0; p < 2; ++p) {
                const int brow = wn + p * 16 + (lane & 7) + ((lane >> 4) << 3);
                const uint32_t bd = sbuf + 2 * MAT_BYTES + brow * RSTRIDE_B
                                  + kk * 32 + (((lane >> 3) & 1) << 4);
                ldsm_x4(bh[p], bd);
                ldsm_x4(bl[p], bd + MAT_BYTES);
            }
            #pragma unroll
            for (int mi = 0; mi < 4; ++mi)
                #pragma unroll
                for (int ni = 0; ni < 4; ++ni) {
                    const uint32_t* bhf = &bh[ni >> 1][(ni & 1) * 2];
                    const uint32_t* blf = &bl[ni >> 1][(ni & 1) * 2];
                    mma16816(acc[mi][ni], ah[mi], bhf);
                    mma16816(acc[mi][ni], ah[mi], blf);
                    mma16816(acc[mi][ni], al[mi], bhf);
                }
        }
    }

    #pragma unroll
    for (int mi = 0; mi < 4; ++mi) {
        const int r0 = row0 + wm + mi * 16 + (lane >> 2);
        #pragma unroll
        for (int ni = 0; ni < 4; ++ni) {
            const int c = col0 + wn + ni * 8 + (lane & 3) * 2;
            if (SPLIT) {
                float v0 = acc[mi][ni][0] * scale, v1 = acc[mi][ni][1] * scale;
                float v2 = acc[mi][ni][2] * scale, v3 = acc[mi][ni][3] * scale;
                __nv_bfloat16 h0 = __float2bfloat16(v0), h1 = __float2bfloat16(v1);
                __nv_bfloat16 h2 = __float2bfloat16(v2), h3 = __float2bfloat16(v3);
                __nv_bfloat16 e0 = __float2bfloat16(v0 - __bfloat162float(h0));
                __nv_bfloat16 e1 = __float2bfloat16(v1 - __bfloat162float(h1));
                __nv_bfloat16 e2 = __float2bfloat16(v2 - __bfloat162float(h2));
                __nv_bfloat16 e3 = __float2bfloat16(v3 - __bfloat162float(h3));
                *(uint32_t*)(Ch + (size_t)r0 * GN + c)       = pack2(h0, h1);
                *(uint32_t*)(Ch + (size_t)(r0 + 8) * GN + c) = pack2(h2, h3);
                *(uint32_t*)(Cl + (size_t)r0 * GN + c)       = pack2(e0, e1);
                *(uint32_t*)(Cl + (size_t)(r0 + 8) * GN + c) = pack2(e2, e3);
            } else {
                float2 v0 = { acc[mi][ni][0], acc[mi][ni][1] };
                float2 v1 = { acc[mi][ni][2], acc[mi][ni][3] };
                *(float2*)(C + (size_t)r0 * GN + c)       = v0;
                *(float2*)(C + (size_t)(r0 + 8) * GN + c) = v1;
            }
        }
    }
}

// ---------------------------------------------------------------------------
// HMMA flash attention.
// Grid (SEQ/128, B*H). 8 warps; warp = 16 q-rows. BKV = 64, double-buffered.
// All operands bf16 hi/lo; scores/softmax in f32 regs; P split in regs.
// Output context written as bf16 hi/lo (consumed by the wo GEMM).
// ---------------------------------------------------------------------------
#define FRS 272                        // smem row stride bytes (136 bf16)
#define FQ_BYTES (128 * FRS)           // 34816
#define FKV_BYTES (64 * FRS)           // 17408
#define F_SMEM (2 * FQ_BYTES + 8 * FKV_BYTES)   // 208896

__global__ __launch_bounds__(256, 1) void flash_hmma(
    const __nv_bfloat16* __restrict__ Qh, const __nv_bfloat16* __restrict__ Ql,
    const __nv_bfloat16* __restrict__ Kh, const __nv_bfloat16* __restrict__ Kl,
    const __nv_bfloat16* __restrict__ Vh, const __nv_bfloat16* __restrict__ Vl,
    __nv_bfloat16* __restrict__ Ch, __nv_bfloat16* __restrict__ Cl)
{
    extern __shared__ char smem[];
    const uint32_t sb = smem_u32(smem);
    const int tid  = threadIdx.x;
    const int wid  = tid >> 5;
    const int lane = tid & 31;
    const int q0   = blockIdx.x * 128;
    const int bh   = blockIdx.y;
    const size_t base = (size_t)(bh >> 4) * SEQ * D_MODEL + (size_t)(bh & 15) * DK;
    const int wq0 = wid * 16;

    // ---- Q tile (hi+lo): 128 rows x 128 bf16 ----
    #pragma unroll
    for (int i = 0; i < 16; ++i) {
        const int id = i * 256 + tid;
        const int mat = id >> 11, rc = id & 2047, r = rc >> 4, c = rc & 15;
        const __nv_bfloat16* src = (mat ? Ql : Qh) + base + (size_t)(q0 + r) * D_MODEL + c * 8;
        cp16(sb + mat * FQ_BYTES + r * FRS + c * 16, src);
    }
    auto load_kv = [&](int kb, int st) {
        const uint32_t s = sb + 2 * FQ_BYTES + st * (4 * FKV_BYTES);
        #pragma unroll
        for (int i = 0; i < 16; ++i) {
            const int id = i * 256 + tid;
            const int mat = id >> 10, rc = id & 1023, r = rc >> 4, c = rc & 15;
            const __nv_bfloat16* gb = (mat == 0) ? Kh : (mat == 1) ? Kl : (mat == 2) ? Vh : Vl;
            cp16(s + mat * FKV_BYTES + r * FRS + c * 16,
                 gb + base + (size_t)(kb + r) * D_MODEL + c * 8);
        }
    };
    load_kv(0, 0);
    asm volatile("cp.async.commit_group;" ::: "memory");

    float o[16][4];
    #pragma unroll
    for (int n = 0; n < 16; ++n)
        #pragma unroll
        for (int j = 0; j < 4; ++j) o[n][j] = 0.f;
    float m0 = -1e30f, m1 = -1e30f, l0 = 0.f, l1 = 0.f;

    for (int s = 0; s < SEQ / 64; ++s) {
        if (s < SEQ / 64 - 1) {
            load_kv((s + 1) * 64, (s + 1) & 1);
            asm volatile("cp.async.commit_group;" ::: "memory");
            asm volatile("cp.async.wait_group 1;" ::: "memory");
        } else {
            asm volatile("cp.async.wait_group 0;" ::: "memory");
        }
        __syncthreads();

        const uint32_t sK = sb + 2 * FQ_BYTES + (s & 1) * (4 * FKV_BYTES);
        const uint32_t sV = sK + 2 * FKV_BYTES;

        // ---- QK^T : sc[8 n8-tiles][4] ----
        float sc[8][4];
        #pragma unroll
        for (int n = 0; n < 8; ++n)
            #pragma unroll
            for (int j = 0; j < 4; ++j) sc[n][j] = 0.f;

        #pragma unroll
        for (int kk = 0; kk < 8; ++kk) {
            uint32_t ah[4], al[4];
            const uint32_t ad = sb + (wq0 + (lane & 15)) * FRS + kk * 32 + (lane >> 4) * 16;
            ldsm_x4(ah, ad);
            ldsm_x4(al, ad + FQ_BYTES);
            #pragma unroll
            for (int p = 0; p < 4; ++p) {
                uint32_t kh4[4], kl4[4];
                const uint32_t bd = sK + (p * 16 + (lane & 7) + ((lane >> 4) << 3)) * FRS
                                  + kk * 32 + (((lane >> 3) & 1) << 4);
                ldsm_x4(kh4, bd);
                ldsm_x4(kl4, bd + FKV_BYTES);
                mma16816(sc[2*p],   ah, &kh4[0]);
                mma16816(sc[2*p],   ah, &kl4[0]);
                mma16816(sc[2*p],   al, &kh4[0]);
                mma16816(sc[2*p+1], ah, &kh4[2]);
                mma16816(sc[2*p+1], ah, &kl4[2]);
                mma16816(sc[2*p+1], al, &kh4[2]);
            }
        }

        // ---- online softmax (rows r0 = lane>>2, r1 = r0+8) ----
        float mx0 = -1e30f, mx1 = -1e30f;
        #pragma unroll
        for (int n = 0; n < 8; ++n) {
            mx0 = fmaxf(mx0, fmaxf(sc[n][0], sc[n][1]));
            mx1 = fmaxf(mx1, fmaxf(sc[n][2], sc[n][3]));
        }
        mx0 = fmaxf(mx0, __shfl_xor_sync(0xffffffffu, mx0, 1));
        mx0 = fmaxf(mx0, __shfl_xor_sync(0xffffffffu, mx0, 2));
        mx1 = fmaxf(mx1, __shfl_xor_sync(0xffffffffu, mx1, 1));
        mx1 = fmaxf(mx1, __shfl_xor_sync(0xffffffffu, mx1, 2));
        const float mn0 = fmaxf(m0, mx0), mn1 = fmaxf(m1, mx1);
        const float a0 = __expf(m0 - mn0), a1 = __expf(m1 - mn1);
        m0 = mn0; m1 = mn1;

        float rs0 = 0.f, rs1 = 0.f;
        uint32_t pah[4][4], pal[4][4];
        #pragma unroll
        for (int n = 0; n < 8; ++n) {
            const float p0 = __expf(sc[n][0] - mn0), p1 = __expf(sc[n][1] - mn0);
            const float p2 = __expf(sc[n][2] - mn1), p3 = __expf(sc[n][3] - mn1);
            rs0 += p0 + p1; rs1 += p2 + p3;
            const __nv_bfloat16 h0 = __float2bfloat16(p0), h1 = __float2bfloat16(p1);
            const __nv_bfloat16 h2 = __float2bfloat16(p2), h3 = __float2bfloat16(p3);
            const __nv_bfloat16 e0 = __float2bfloat16(p0 - __bfloat162float(h0));
            const __nv_bfloat16 e1 = __float2bfloat16(p1 - __bfloat162float(h1));
            const __nv_bfloat16 e2 = __float2bfloat16(p2 - __bfloat162float(h2));
            const __nv_bfloat16 e3 = __float2bfloat16(p3 - __bfloat162float(h3));
            const int t = n >> 1, off = (n & 1) * 2;
            pah[t][off]     = pack2(h0, h1);
            pah[t][off + 1] = pack2(h2, h3);
            pal[t][off]     = pack2(e0, e1);
            pal[t][off + 1] = pack2(e2, e3);
        }
        rs0 += __shfl_xor_sync(0xffffffffu, rs0, 1);
        rs0 += __shfl_xor_sync(0xffffffffu, rs0, 2);
        rs1 += __shfl_xor_sync(0xffffffffu, rs1, 1);
        rs1 += __shfl_xor_sync(0xffffffffu, rs1, 2);
        l0 = l0 * a0 + rs0;
        l1 = l1 * a1 + rs1;
        #pragma unroll
        for (int n = 0; n < 16; ++n) {
            o[n][0] *= a0; o[n][1] *= a0; o[n][2] *= a1; o[n][3] *= a1;
        }

        // ---- PV : o += P @ V (V via trans ldmatrix) ----
        #pragma unroll
        for (int t = 0; t < 4; ++t) {
            #pragma unroll
            for (int dq = 0; dq < 8; ++dq) {
                uint32_t vh4[4], vl4[4];
                const uint32_t vd = sV + (t * 16 + (lane & 15)) * FRS + dq * 32 + (lane >> 4) * 16;
                ldsm_x4_t(vh4, vd);
                ldsm_x4_t(vl4, vd + FKV_BYTES);
                mma16816(o[2*dq],   pah[t], &vh4[0]);
                mma16816(o[2*dq],   pah[t], &vl4[0]);
                mma16816(o[2*dq],   pal[t], &vh4[0]);
                mma16816(o[2*dq+1], pah[t], &vh4[2]);
                mma16816(o[2*dq+1], pah[t], &vl4[2]);
                mma16816(o[2*dq+1], pal[t], &vh4[2]);
            }
        }
        __syncthreads();
    }

    // ---- finalize: /l, split to bf16 hi/lo, write context ----
    const float rl0 = 1.f / l0, rl1 = 1.f / l1;
    const int gr0 = q0 + wq0 + (lane >> 2);
    const int c0  = (lane & 3) * 2;
    #pragma unroll
    for (int n = 0; n < 16; ++n) {
        const int col = n * 8 + c0;
        const float f0 = o[n][0] * rl0, f1 = o[n][1] * rl0;
        const float f2 = o[n][2] * rl1, f3 = o[n][3] * rl1;
        const __nv_bfloat16 h0 = __float2bfloat16(f0), h1 = __float2bfloat16(f1);
        const __nv_bfloat16 h2 = __float2bfloat16(f2), h3 = __float2bfloat16(f3);
        const __nv_bfloat16 e0 = __float2bfloat16(f0 - __bfloat162float(h0));
        const __nv_bfloat16 e1 = __float2bfloat16(f1 - __bfloat162float(h1));
        const __nv_bfloat16 e2 = __float2bfloat16(f2 - __bfloat162float(h2));
        const __nv_bfloat16 e3 = __float2bfloat16(f3 - __bfloat162float(h3));
        *(uint32_t*)(Ch + base + (size_t)gr0 * D_MODEL + col)       = pack2(h0, h1);
        *(uint32_t*)(Ch + base + (size_t)(gr0 + 8) * D_MODEL + col) = pack2(h2, h3);
        *(uint32_t*)(Cl + base + (size_t)gr0 * D_MODEL + col)       = pack2(e0, e1);
        *(uint32_t*)(Cl + base + (size_t)(gr0 + 8) * D_MODEL + col) = pack2(e2, e3);
    }
}

// ---------------------------------------------------------------------------
// Launch
// ---------------------------------------------------------------------------
extern "C" void kernel_launch(void* const* d_in, const int* in_sizes, int n_in,
                              void* d_out, int out_size)
{
    const float* x  = (const float*)d_in[0];
    const float* wq = (const float*)d_in[1];
    const float* wk = (const float*)d_in[2];
    const float* wv = (const float*)d_in[3];
    const float* wo = (const float*)d_in[4];
    float* out = (float*)d_out;

    __nv_bfloat16 *Qh, *Ql, *Kh, *Kl, *Vh, *Vl, *ch, *cl;
    __nv_bfloat16 *xh, *xl, *wqh, *wql, *wkh, *wkl, *wvh, *wvl, *woh, *wol;
    cudaGetSymbolAddress((void**)&Qh, g_Qh);   cudaGetSymbolAddress((void**)&Ql, g_Ql);
    cudaGetSymbolAddress((void**)&Kh, g_Kh);   cudaGetSymbolAddress((void**)&Kl, g_Kl);
    cudaGetSymbolAddress((void**)&Vh, g_Vh);   cudaGetSymbolAddress((void**)&Vl, g_Vl);
    cudaGetSymbolAddress((void**)&ch, g_ch);   cudaGetSymbolAddress((void**)&cl, g_cl);
    cudaGetSymbolAddress((void**)&xh, g_xh);   cudaGetSymbolAddress((void**)&xl, g_xl);
    cudaGetSymbolAddress((void**)&wqh, g_wqh); cudaGetSymbolAddress((void**)&wql, g_wql);
    cudaGetSymbolAddress((void**)&wkh, g_wkh); cudaGetSymbolAddress((void**)&wkl, g_wkl);
    cudaGetSymbolAddress((void**)&wvh, g_wvh); cudaGetSymbolAddress((void**)&wvl, g_wvl);
    cudaGetSymbolAddress((void**)&woh, g_woh); cudaGetSymbolAddress((void**)&wol, g_wol);

    cudaFuncSetAttribute(gemm_hmma<true>,  cudaFuncAttributeMaxDynamicSharedMemorySize, GEMM_SMEM);
    cudaFuncSetAttribute(gemm_hmma<false>, cudaFuncAttributeMaxDynamicSharedMemorySize, GEMM_SMEM);
    cudaFuncSetAttribute(flash_hmma, cudaFuncAttributeMaxDynamicSharedMemorySize, F_SMEM);

    const int n4x = (M_TOT * D_MODEL) / 4;
    const int n4w = (D_MODEL * D_MODEL) / 4;

    split_kernel<<<n4x / 256, 256>>>((const float4*)x,  (uint2*)xh,  (uint2*)xl,  n4x);
    split_kernel<<<n4w / 256, 256>>>((const float4*)wq, (uint2*)wqh, (uint2*)wql, n4w);
    split_kernel<<<n4w / 256, 256>>>((const float4*)wk, (uint2*)wkh, (uint2*)wkl, n4w);
    split_kernel<<<n4w / 256, 256>>>((const float4*)wv, (uint2*)wvh, (uint2*)wvl, n4w);
    split_kernel<<<n4w / 256, 256>>>((const float4*)wo, (uint2*)woh, (uint2*)wol, n4w);

    const dim3 gg(M_TOT / 128, GN / 128);
    gemm_hmma<true><<<gg, 256, GEMM_SMEM>>>(xh, xl, wqh, wql, nullptr, Qh, Ql, QSCALE);
    gemm_hmma<true><<<gg, 256, GEMM_SMEM>>>(xh, xl, wkh, wkl, nullptr, Kh, Kl, 1.0f);
    gemm_hmma<true><<<gg, 256, GEMM_SMEM>>>(xh, xl, wvh, wvl, nullptr, Vh, Vl, 1.0f);

    flash_hmma<<<dim3(SEQ / 128, BATCH * NHEAD), 256, F_SMEM>>>(Qh, Ql, Kh, Kl, Vh, Vl, ch, cl);

    gemm_hmma<false><<<gg, 256, GEMM_SMEM>>>(ch, cl, woh, wol, out, nullptr, nullptr, 1.0f);
}